// round 1
// baseline (speedup 1.0000x reference)
#include <cuda_runtime.h>
#include <math.h>

#define NMAX 100000
#define EMAX 1600000

// ---------------- scratch (no allocations allowed) ----------------
__device__ __align__(16) float g_hA[NMAX * 8];
__device__ __align__(16) float g_hB[NMAX * 8];
__device__ float g_w[EMAX];
__device__ float g_he[EMAX];
__device__ float g_agg[NMAX];
__device__ float g_s[NMAX];
__device__ unsigned int g_m[NMAX];

// ---------------- ordered-float helpers for atomicMax ----------------
__device__ __forceinline__ unsigned f2o(float f) {
    unsigned u = __float_as_uint(f);
    return (u & 0x80000000u) ? ~u : (u | 0x80000000u);
}
__device__ __forceinline__ float o2f(unsigned o) {
    return (o & 0x80000000u) ? __uint_as_float(o ^ 0x80000000u)
                             : __uint_as_float(~o);
}

// ---------------- tiny utility kernels ----------------
__global__ void k_zero_f(float* p, int n) {
    int i = blockIdx.x * blockDim.x + threadIdx.x;
    if (i < n) p[i] = 0.f;
}
__global__ void k_zero_u(unsigned* p, int n) {
    int i = blockIdx.x * blockDim.x + threadIdx.x;
    if (i < n) p[i] = 0u;
}

__global__ void k_segmax(const float* __restrict__ dist,
                         const int* __restrict__ dst,
                         unsigned* __restrict__ m, int E) {
    int e = blockIdx.x * blockDim.x + threadIdx.x;
    if (e >= E) return;
    atomicMax(&m[dst[e]], f2o(dist[e]));
}

__global__ void k_segexp(const float* __restrict__ dist,
                         const int* __restrict__ dst,
                         const unsigned* __restrict__ m,
                         float* __restrict__ w, float* __restrict__ s, int E) {
    int e = blockIdx.x * blockDim.x + threadIdx.x;
    if (e >= E) return;
    int d = dst[e];
    float ev = expf(dist[e] - o2f(m[d]));
    w[e] = ev;
    atomicAdd(&s[d], ev);
}

__global__ void k_segnorm(float* __restrict__ w, const float* __restrict__ s,
                          const int* __restrict__ dst, int E) {
    int e = blockIdx.x * blockDim.x + threadIdx.x;
    if (e >= E) return;
    w[e] = w[e] / s[dst[e]];
}

// h_out[dst] += w[e] * h[src]   (8 lanes)
__global__ void k_agg8(const float* __restrict__ w, const float* __restrict__ h,
                       const int* __restrict__ src, const int* __restrict__ dst,
                       float* __restrict__ ho, int E) {
    int e = blockIdx.x * blockDim.x + threadIdx.x;
    if (e >= E) return;
    float we = w[e];
    int sn = src[e], dn = dst[e];
    const float4* hp = (const float4*)(h + (size_t)sn * 8);
    float4 a = hp[0], b = hp[1];
    float* o = ho + (size_t)dn * 8;
    atomicAdd(o + 0, we * a.x);
    atomicAdd(o + 1, we * a.y);
    atomicAdd(o + 2, we * a.z);
    atomicAdd(o + 3, we * a.w);
    atomicAdd(o + 4, we * b.x);
    atomicAdd(o + 5, we * b.y);
    atomicAdd(o + 6, we * b.z);
    atomicAdd(o + 7, we * b.w);
}

// ---------------- generic per-node MLP: D0 -> 64 -> 64 -> DOUT (relu x3) ----
// Input x[i] = i < SPLIT ? xa[n*SPLIT + i] : xb[n*8 + (i-SPLIT)]
template <int D0, int SPLIT, int DOUT>
__global__ __launch_bounds__(256) void k_node_mlp(
    const float* __restrict__ xa, const float* __restrict__ xb,
    const float* __restrict__ w1, const float* __restrict__ b1,
    const float* __restrict__ w2, const float* __restrict__ b2,
    const float* __restrict__ w3, const float* __restrict__ b3,
    float* __restrict__ out, int N) {
    __shared__ __align__(16) float s_w1[D0 * 64];
    __shared__ __align__(16) float s_w2t[64 * 64];
    __shared__ __align__(16) float s_w3[64 * DOUT];
    __shared__ float s_b1[64], s_b2[64], s_b3[DOUT];

    for (int i = threadIdx.x; i < D0 * 64; i += blockDim.x) s_w1[i] = w1[i];
    for (int i = threadIdx.x; i < 64 * 64; i += blockDim.x) {
        int k = i >> 6, j = i & 63;
        s_w2t[i] = w2[j * 64 + k];  // transpose: s_w2t[k][j]
    }
    for (int i = threadIdx.x; i < 64 * DOUT; i += blockDim.x) s_w3[i] = w3[i];
    if (threadIdx.x < 64) {
        s_b1[threadIdx.x] = b1[threadIdx.x];
        s_b2[threadIdx.x] = b2[threadIdx.x];
    }
    if (threadIdx.x < DOUT) s_b3[threadIdx.x] = b3[threadIdx.x];
    __syncthreads();

    int n = blockIdx.x * blockDim.x + threadIdx.x;
    if (n >= N) return;

    float xv[D0];
#pragma unroll
    for (int i = 0; i < SPLIT; i++) xv[i] = xa[(size_t)n * SPLIT + i];
    if constexpr (SPLIT < D0) {
#pragma unroll
        for (int i = 0; i < D0 - SPLIT; i++)
            xv[SPLIT + i] = xb[(size_t)n * 8 + i];
    }

    float h1[64];
#pragma unroll
    for (int k = 0; k < 64; k++) h1[k] = s_b1[k];
#pragma unroll
    for (int i = 0; i < D0; i++) {
        float xi = xv[i];
#pragma unroll
        for (int k = 0; k < 64; k += 4) {
            float4 wv = *(const float4*)&s_w1[i * 64 + k];
            h1[k + 0] = fmaf(xi, wv.x, h1[k + 0]);
            h1[k + 1] = fmaf(xi, wv.y, h1[k + 1]);
            h1[k + 2] = fmaf(xi, wv.z, h1[k + 2]);
            h1[k + 3] = fmaf(xi, wv.w, h1[k + 3]);
        }
    }
#pragma unroll
    for (int k = 0; k < 64; k++) h1[k] = fmaxf(h1[k], 0.f);

    float o[DOUT];
#pragma unroll
    for (int d = 0; d < DOUT; d++) o[d] = s_b3[d];

#pragma unroll 4
    for (int k = 0; k < 64; k++) {
        float acc = s_b2[k];
#pragma unroll
        for (int j = 0; j < 64; j += 4) {
            float4 wv = *(const float4*)&s_w2t[k * 64 + j];
            acc = fmaf(h1[j + 0], wv.x, acc);
            acc = fmaf(h1[j + 1], wv.y, acc);
            acc = fmaf(h1[j + 2], wv.z, acc);
            acc = fmaf(h1[j + 3], wv.w, acc);
        }
        float h2 = fmaxf(acc, 0.f);
#pragma unroll
        for (int d = 0; d < DOUT; d++) o[d] = fmaf(h2, s_w3[k * DOUT + d], o[d]);
    }
#pragma unroll
    for (int d = 0; d < DOUT; d++)
        out[(size_t)n * DOUT + d] = fmaxf(o[d], 0.f);
}

// ---------------- edge MLP: [he, h[src], h[dst]] (17) -> 64 -> 64 -> 1 -------
// writes he_out[e] and atomicAdds into agg[dst].
__global__ __launch_bounds__(256) void k_edge_mlp(
    const float* __restrict__ he_in, const float* __restrict__ h,
    const int* __restrict__ src, const int* __restrict__ dst,
    const float* __restrict__ w1, const float* __restrict__ b1,
    const float* __restrict__ w2, const float* __restrict__ b2,
    const float* __restrict__ w3, const float* __restrict__ b3,
    float* __restrict__ he_out, float* __restrict__ agg, int E) {
    __shared__ __align__(16) float s_w1[17 * 64];
    __shared__ __align__(16) float s_w2t[64 * 64];
    __shared__ float s_b1[64], s_b2[64], s_w3[64];

    for (int i = threadIdx.x; i < 17 * 64; i += blockDim.x) s_w1[i] = w1[i];
    for (int i = threadIdx.x; i < 64 * 64; i += blockDim.x) {
        int k = i >> 6, j = i & 63;
        s_w2t[i] = w2[j * 64 + k];
    }
    if (threadIdx.x < 64) {
        s_b1[threadIdx.x] = b1[threadIdx.x];
        s_b2[threadIdx.x] = b2[threadIdx.x];
        s_w3[threadIdx.x] = w3[threadIdx.x];
    }
    __syncthreads();

    int e = blockIdx.x * blockDim.x + threadIdx.x;
    if (e >= E) return;

    float xv[17];
    xv[0] = he_in[e];
    int sn = src[e], dn = dst[e];
    {
        const float4* p = (const float4*)(h + (size_t)sn * 8);
        float4 a = p[0], b4 = p[1];
        xv[1] = a.x; xv[2] = a.y; xv[3] = a.z; xv[4] = a.w;
        xv[5] = b4.x; xv[6] = b4.y; xv[7] = b4.z; xv[8] = b4.w;
        p = (const float4*)(h + (size_t)dn * 8);
        a = p[0]; b4 = p[1];
        xv[9] = a.x; xv[10] = a.y; xv[11] = a.z; xv[12] = a.w;
        xv[13] = b4.x; xv[14] = b4.y; xv[15] = b4.z; xv[16] = b4.w;
    }

    float h1[64];
#pragma unroll
    for (int k = 0; k < 64; k++) h1[k] = s_b1[k];
#pragma unroll
    for (int i = 0; i < 17; i++) {
        float xi = xv[i];
#pragma unroll
        for (int k = 0; k < 64; k += 4) {
            float4 wv = *(const float4*)&s_w1[i * 64 + k];
            h1[k + 0] = fmaf(xi, wv.x, h1[k + 0]);
            h1[k + 1] = fmaf(xi, wv.y, h1[k + 1]);
            h1[k + 2] = fmaf(xi, wv.z, h1[k + 2]);
            h1[k + 3] = fmaf(xi, wv.w, h1[k + 3]);
        }
    }
#pragma unroll
    for (int k = 0; k < 64; k++) h1[k] = fmaxf(h1[k], 0.f);

    float out = b3[0];
#pragma unroll 4
    for (int k = 0; k < 64; k++) {
        float acc = s_b2[k];
#pragma unroll
        for (int j = 0; j < 64; j += 4) {
            float4 wv = *(const float4*)&s_w2t[k * 64 + j];
            acc = fmaf(h1[j + 0], wv.x, acc);
            acc = fmaf(h1[j + 1], wv.y, acc);
            acc = fmaf(h1[j + 2], wv.z, acc);
            acc = fmaf(h1[j + 3], wv.w, acc);
        }
        out = fmaf(fmaxf(acc, 0.f), s_w3[k], out);
    }
    out = fmaxf(out, 0.f);
    he_out[e] = out;
    atomicAdd(&agg[dn], out);
}

// ---------------- launch ----------------
extern "C" void kernel_launch(void* const* d_in, const int* in_sizes, int n_in,
                              void* d_out, int out_size) {
    const float* node_feat = (const float*)d_in[0];
    const float* edge_feat = (const float*)d_in[1];
    const float* edge_dist = (const float*)d_in[2];
    const int* src = (const int*)d_in[3];
    const int* dst = (const int*)d_in[4];

    const float* w_enc1 = (const float*)d_in[5];
    const float* b_enc1 = (const float*)d_in[6];
    const float* w_enc2 = (const float*)d_in[7];
    const float* b_enc2 = (const float*)d_in[8];
    const float* w_enc3 = (const float*)d_in[9];
    const float* b_enc3 = (const float*)d_in[10];

    const float* w_dec1 = (const float*)d_in[11];
    const float* b_dec1 = (const float*)d_in[12];
    const float* w_dec2 = (const float*)d_in[13];
    const float* b_dec2 = (const float*)d_in[14];
    const float* w_dec3 = (const float*)d_in[15];
    const float* b_dec3 = (const float*)d_in[16];

    const float* w_nod1 = (const float*)d_in[17];
    const float* b_nod1 = (const float*)d_in[18];
    const float* w_nod2 = (const float*)d_in[19];
    const float* b_nod2 = (const float*)d_in[20];
    const float* w_nod3 = (const float*)d_in[21];
    const float* b_nod3 = (const float*)d_in[22];

    const float* w_edg1 = (const float*)d_in[23];
    const float* b_edg1 = (const float*)d_in[24];
    const float* w_edg2 = (const float*)d_in[25];
    const float* b_edg2 = (const float*)d_in[26];
    const float* w_edg3 = (const float*)d_in[27];
    const float* b_edg3 = (const float*)d_in[28];

    int N = in_sizes[0] / 3;
    int E = in_sizes[1];

    float *hA, *hB, *wbuf, *hebuf, *aggbuf, *sbuf;
    unsigned* mbuf;
    cudaGetSymbolAddress((void**)&hA, g_hA);
    cudaGetSymbolAddress((void**)&hB, g_hB);
    cudaGetSymbolAddress((void**)&wbuf, g_w);
    cudaGetSymbolAddress((void**)&hebuf, g_he);
    cudaGetSymbolAddress((void**)&aggbuf, g_agg);
    cudaGetSymbolAddress((void**)&sbuf, g_s);
    cudaGetSymbolAddress((void**)&mbuf, g_m);

    int gN = (N + 255) / 256;
    int gN8 = (N * 8 + 255) / 256;
    int gE = (E + 255) / 256;

    // encoder: [N,3] -> hA [N,8]
    k_node_mlp<3, 3, 8><<<gN, 256>>>(node_feat, nullptr, w_enc1, b_enc1, w_enc2,
                                     b_enc2, w_enc3, b_enc3, hA, N);

    // edge softmax weights
    k_zero_u<<<gN, 256>>>(mbuf, N);
    k_segmax<<<gE, 256>>>(edge_dist, dst, mbuf, E);
    k_zero_f<<<gN, 256>>>(sbuf, N);
    k_segexp<<<gE, 256>>>(edge_dist, dst, mbuf, wbuf, sbuf, E);
    k_segnorm<<<gE, 256>>>(wbuf, sbuf, dst, E);

    // h = segsum(w * hA[src], dst) -> hB
    k_zero_f<<<gN8, 256>>>(hB, N * 8);
    k_agg8<<<gE, 256>>>(wbuf, hA, src, dst, hB, E);

    // iteration 1 (h = hB, he = edge_feat)
    k_zero_f<<<gN, 256>>>(aggbuf, N);
    k_edge_mlp<<<gE, 256>>>(edge_feat, hB, src, dst, w_edg1, b_edg1, w_edg2,
                            b_edg2, w_edg3, b_edg3, hebuf, aggbuf, E);
    k_node_mlp<9, 1, 8><<<gN, 256>>>(aggbuf, hB, w_nod1, b_nod1, w_nod2, b_nod2,
                                     w_nod3, b_nod3, hA, N);

    // iteration 2 (h = hA, he = hebuf)
    k_zero_f<<<gN, 256>>>(aggbuf, N);
    k_edge_mlp<<<gE, 256>>>(hebuf, hA, src, dst, w_edg1, b_edg1, w_edg2, b_edg2,
                            w_edg3, b_edg3, hebuf, aggbuf, E);
    k_node_mlp<9, 1, 8><<<gN, 256>>>(aggbuf, hA, w_nod1, b_nod1, w_nod2, b_nod2,
                                     w_nod3, b_nod3, hB, N);

    // final softmax aggregation: hA = segsum(w * hB[src], dst)
    k_zero_f<<<gN8, 256>>>(hA, N * 8);
    k_agg8<<<gE, 256>>>(wbuf, hB, src, dst, hA, E);

    // decoder: hA [N,8] -> out [N,1]
    k_node_mlp<8, 8, 1><<<gN, 256>>>(hA, nullptr, w_dec1, b_dec1, w_dec2, b_dec2,
                                     w_dec3, b_dec3, (float*)d_out, N);
}

// round 2
// speedup vs baseline: 1.2160x; 1.2160x over previous
#include <cuda_runtime.h>
#include <math.h>

#define NMAX 100000
#define EMAX 1600000

typedef unsigned long long u64;

// ---------------- scratch (no allocations allowed) ----------------
__device__ __align__(16) float g_hA[NMAX * 8];
__device__ __align__(16) float g_hB[NMAX * 8];
__device__ float g_w[EMAX];
__device__ float g_he[EMAX];
__device__ float g_agg[NMAX];
__device__ float g_s[NMAX];
__device__ unsigned int g_m[NMAX];

// ---------------- packed f32x2 helpers ----------------
__device__ __forceinline__ u64 pk2(float lo, float hi) {
    u64 r;
    asm("mov.b64 %0, {%1,%2};" : "=l"(r) : "f"(lo), "f"(hi));
    return r;
}
__device__ __forceinline__ void upk2(u64 v, float& lo, float& hi) {
    asm("mov.b64 {%0,%1}, %2;" : "=f"(lo), "=f"(hi) : "l"(v));
}
__device__ __forceinline__ u64 dup2(float v) { return pk2(v, v); }
__device__ __forceinline__ u64 ffma2(u64 a, u64 b, u64 c) {
    u64 d;
    asm("fma.rn.f32x2 %0, %1, %2, %3;" : "=l"(d) : "l"(a), "l"(b), "l"(c));
    return d;
}
__device__ __forceinline__ u64 relu2(u64 v) {
    float a, b;
    upk2(v, a, b);
    return pk2(fmaxf(a, 0.f), fmaxf(b, 0.f));
}

// ---------------- ordered-float helpers for atomicMax ----------------
__device__ __forceinline__ unsigned f2o(float f) {
    unsigned u = __float_as_uint(f);
    return (u & 0x80000000u) ? ~u : (u | 0x80000000u);
}
__device__ __forceinline__ float o2f(unsigned o) {
    return (o & 0x80000000u) ? __uint_as_float(o ^ 0x80000000u)
                             : __uint_as_float(~o);
}

// ---------------- softmax helper kernels ----------------
__global__ void k_segmax(const float* __restrict__ dist,
                         const int* __restrict__ dst,
                         unsigned* __restrict__ m, int E) {
    int e = blockIdx.x * blockDim.x + threadIdx.x;
    if (e >= E) return;
    atomicMax(&m[dst[e]], f2o(dist[e]));
}

__global__ void k_segexp(const float* __restrict__ dist,
                         const int* __restrict__ dst,
                         const unsigned* __restrict__ m,
                         float* __restrict__ w, float* __restrict__ s, int E) {
    int e = blockIdx.x * blockDim.x + threadIdx.x;
    if (e >= E) return;
    int d = dst[e];
    float ev = expf(dist[e] - o2f(m[d]));
    w[e] = ev;  // unnormalized; node-side divide later
    atomicAdd(&s[d], ev);
}

// h_out[dst] += w[e] * h[src]   (8 lanes, unnormalized w)
__global__ void k_agg8(const float* __restrict__ w, const float* __restrict__ h,
                       const int* __restrict__ src, const int* __restrict__ dst,
                       float* __restrict__ ho, int E) {
    int e = blockIdx.x * blockDim.x + threadIdx.x;
    if (e >= E) return;
    float we = w[e];
    int sn = src[e], dn = dst[e];
    const float4* hp = (const float4*)(h + (size_t)sn * 8);
    float4 a = hp[0], b = hp[1];
    float* o = ho + (size_t)dn * 8;
    atomicAdd(o + 0, we * a.x);
    atomicAdd(o + 1, we * a.y);
    atomicAdd(o + 2, we * a.z);
    atomicAdd(o + 3, we * a.w);
    atomicAdd(o + 4, we * b.x);
    atomicAdd(o + 5, we * b.y);
    atomicAdd(o + 6, we * b.z);
    atomicAdd(o + 7, we * b.w);
}

// h[n][0..7] *= (s[n] > 0 ? 1/s[n] : 0)
__global__ void k_scale8(float* __restrict__ h, const float* __restrict__ s,
                         int N) {
    int i = blockIdx.x * blockDim.x + threadIdx.x;
    if (i >= N * 8) return;
    float sv = s[i >> 3];
    float inv = (sv > 0.f) ? (1.f / sv) : 0.f;
    h[i] *= inv;
}

// ---------------- generic per-node MLP: D0 -> 64 -> 64 -> DOUT (relu x3) ----
// Input x[i] = i < SPLIT ? xa[n*SPLIT + i] : xb[n*8 + (i-SPLIT)]
template <int D0, int SPLIT, int DOUT>
__global__ __launch_bounds__(128) void k_node_mlp(
    const float* __restrict__ xa, const float* __restrict__ xb,
    const float* __restrict__ w1, const float* __restrict__ b1,
    const float* __restrict__ w2, const float* __restrict__ b2,
    const float* __restrict__ w3, const float* __restrict__ b3,
    float* __restrict__ out, int N) {
    __shared__ __align__(16) float s_w1[D0 * 64];
    __shared__ __align__(16) float s_w2t[64 * 64];
    __shared__ __align__(16) float s_w3[64 * DOUT];
    __shared__ __align__(16) float s_b1[64];
    __shared__ __align__(16) float s_b3p[(DOUT + 1) & ~1];
    __shared__ float s_b2[64];

    for (int i = threadIdx.x; i < D0 * 64; i += 128) s_w1[i] = w1[i];
    for (int i = threadIdx.x; i < 64 * 64; i += 128) {
        int k = i >> 6, j = i & 63;
        s_w2t[i] = w2[j * 64 + k];  // transpose: s_w2t[k][j]
    }
    for (int i = threadIdx.x; i < 64 * DOUT; i += 128) s_w3[i] = w3[i];
    if (threadIdx.x < 64) {
        s_b1[threadIdx.x] = b1[threadIdx.x];
        s_b2[threadIdx.x] = b2[threadIdx.x];
    }
    if (threadIdx.x < DOUT) s_b3p[threadIdx.x] = b3[threadIdx.x];
    __syncthreads();

    int n = blockIdx.x * 128 + threadIdx.x;
    if (n >= N) return;

    float xv[D0];
#pragma unroll
    for (int i = 0; i < SPLIT; i++) xv[i] = xa[(size_t)n * SPLIT + i];
    if constexpr (SPLIT < D0) {
#pragma unroll
        for (int i = 0; i < D0 - SPLIT; i++)
            xv[SPLIT + i] = xb[(size_t)n * 8 + i];
    }

    const u64* w1p = (const u64*)s_w1;
    const u64* b1p = (const u64*)s_b1;
    u64 h1[32];
#pragma unroll
    for (int kp = 0; kp < 32; kp++) h1[kp] = b1p[kp];
#pragma unroll 4
    for (int i = 0; i < D0; i++) {
        u64 x2 = dup2(xv[i]);
#pragma unroll
        for (int kp = 0; kp < 32; kp++)
            h1[kp] = ffma2(x2, w1p[i * 32 + kp], h1[kp]);
    }
#pragma unroll
    for (int kp = 0; kp < 32; kp++) h1[kp] = relu2(h1[kp]);

    const u64* w2p = (const u64*)s_w2t;

    if constexpr (DOUT == 1) {
        float o = s_b3p[0];
#pragma unroll 4
        for (int k = 0; k < 64; k++) {
            u64 acc = 0ull;
#pragma unroll
            for (int jp = 0; jp < 32; jp++)
                acc = ffma2(h1[jp], w2p[k * 32 + jp], acc);
            float al, ah;
            upk2(acc, al, ah);
            float h2 = fmaxf(al + ah + s_b2[k], 0.f);
            o = fmaf(h2, s_w3[k], o);
        }
        out[n] = fmaxf(o, 0.f);
    } else {
        const u64* w3p = (const u64*)s_w3;
        const u64* b3p = (const u64*)s_b3p;
        u64 op[DOUT / 2];
#pragma unroll
        for (int dp = 0; dp < DOUT / 2; dp++) op[dp] = b3p[dp];
#pragma unroll 4
        for (int k = 0; k < 64; k++) {
            u64 acc = 0ull;
#pragma unroll
            for (int jp = 0; jp < 32; jp++)
                acc = ffma2(h1[jp], w2p[k * 32 + jp], acc);
            float al, ah;
            upk2(acc, al, ah);
            u64 h2d = dup2(fmaxf(al + ah + s_b2[k], 0.f));
#pragma unroll
            for (int dp = 0; dp < DOUT / 2; dp++)
                op[dp] = ffma2(h2d, w3p[k * (DOUT / 2) + dp], op[dp]);
        }
#pragma unroll
        for (int dp = 0; dp < DOUT / 2; dp++) {
            float a, b;
            upk2(op[dp], a, b);
            out[(size_t)n * DOUT + 2 * dp] = fmaxf(a, 0.f);
            out[(size_t)n * DOUT + 2 * dp + 1] = fmaxf(b, 0.f);
        }
    }
}

// ---------------- edge MLP: [he, h[src], h[dst]] (17) -> 64 -> 64 -> 1 ------
// 2 edges per thread (amortizes SMEM weight loads); packed f32x2 FMAs.
// writes he_out[e] and atomicAdds into agg[dst].
__global__ __launch_bounds__(128) void k_edge_mlp(
    const float* __restrict__ he_in, const float* __restrict__ h,
    const int* __restrict__ src, const int* __restrict__ dst,
    const float* __restrict__ w1, const float* __restrict__ b1,
    const float* __restrict__ w2, const float* __restrict__ b2,
    const float* __restrict__ w3, const float* __restrict__ b3,
    float* __restrict__ he_out, float* __restrict__ agg, int E) {
    __shared__ __align__(16) float s_w1[17 * 64];
    __shared__ __align__(16) float s_w2t[64 * 64];
    __shared__ __align__(16) float s_b1[64];
    __shared__ float s_b2[64], s_w3[64], s_b3;

    for (int i = threadIdx.x; i < 17 * 64; i += 128) s_w1[i] = w1[i];
    for (int i = threadIdx.x; i < 64 * 64; i += 128) {
        int k = i >> 6, j = i & 63;
        s_w2t[i] = w2[j * 64 + k];
    }
    if (threadIdx.x < 64) {
        s_b1[threadIdx.x] = b1[threadIdx.x];
        s_b2[threadIdx.x] = b2[threadIdx.x];
        s_w3[threadIdx.x] = w3[threadIdx.x];
    }
    if (threadIdx.x == 0) s_b3 = b3[0];
    __syncthreads();

    int t = blockIdx.x * 128 + threadIdx.x;
    int e0 = 2 * t;
    if (e0 >= E) return;
    bool has1 = (e0 + 1 < E);
    int e1 = has1 ? (e0 + 1) : e0;

    float x0[17], x1[17];
    x0[0] = he_in[e0];
    x1[0] = he_in[e1];
    int s0 = src[e0], d0 = dst[e0];
    int s1 = src[e1], d1 = dst[e1];
    {
        const float4* p = (const float4*)(h + (size_t)s0 * 8);
        float4 a = p[0], b4 = p[1];
        x0[1] = a.x; x0[2] = a.y; x0[3] = a.z; x0[4] = a.w;
        x0[5] = b4.x; x0[6] = b4.y; x0[7] = b4.z; x0[8] = b4.w;
        p = (const float4*)(h + (size_t)d0 * 8);
        a = p[0]; b4 = p[1];
        x0[9] = a.x; x0[10] = a.y; x0[11] = a.z; x0[12] = a.w;
        x0[13] = b4.x; x0[14] = b4.y; x0[15] = b4.z; x0[16] = b4.w;
        p = (const float4*)(h + (size_t)s1 * 8);
        a = p[0]; b4 = p[1];
        x1[1] = a.x; x1[2] = a.y; x1[3] = a.z; x1[4] = a.w;
        x1[5] = b4.x; x1[6] = b4.y; x1[7] = b4.z; x1[8] = b4.w;
        p = (const float4*)(h + (size_t)d1 * 8);
        a = p[0]; b4 = p[1];
        x1[9] = a.x; x1[10] = a.y; x1[11] = a.z; x1[12] = a.w;
        x1[13] = b4.x; x1[14] = b4.y; x1[15] = b4.z; x1[16] = b4.w;
    }

    const u64* w1p = (const u64*)s_w1;
    const u64* b1p = (const u64*)s_b1;
    u64 h0[32], h1v[32];
#pragma unroll
    for (int kp = 0; kp < 32; kp++) {
        h0[kp] = b1p[kp];
        h1v[kp] = b1p[kp];
    }
#pragma unroll 4
    for (int i = 0; i < 17; i++) {
        u64 xa = dup2(x0[i]);
        u64 xb = dup2(x1[i]);
#pragma unroll
        for (int kp = 0; kp < 32; kp++) {
            u64 w = w1p[i * 32 + kp];
            h0[kp] = ffma2(xa, w, h0[kp]);
            h1v[kp] = ffma2(xb, w, h1v[kp]);
        }
    }
#pragma unroll
    for (int kp = 0; kp < 32; kp++) {
        h0[kp] = relu2(h0[kp]);
        h1v[kp] = relu2(h1v[kp]);
    }

    const u64* w2p = (const u64*)s_w2t;
    float out0 = s_b3, out1 = s_b3;
#pragma unroll 2
    for (int k = 0; k < 64; k++) {
        u64 acc0 = 0ull, acc1 = 0ull;
#pragma unroll
        for (int jp = 0; jp < 32; jp++) {
            u64 w = w2p[k * 32 + jp];
            acc0 = ffma2(h0[jp], w, acc0);
            acc1 = ffma2(h1v[jp], w, acc1);
        }
        float al, ah, bl, bh;
        upk2(acc0, al, ah);
        upk2(acc1, bl, bh);
        float w3k = s_w3[k], b2k = s_b2[k];
        out0 = fmaf(fmaxf(al + ah + b2k, 0.f), w3k, out0);
        out1 = fmaf(fmaxf(bl + bh + b2k, 0.f), w3k, out1);
    }

    out0 = fmaxf(out0, 0.f);
    he_out[e0] = out0;
    atomicAdd(&agg[d0], out0);
    if (has1) {
        out1 = fmaxf(out1, 0.f);
        he_out[e1] = out1;
        atomicAdd(&agg[d1], out1);
    }
}

// ---------------- launch ----------------
extern "C" void kernel_launch(void* const* d_in, const int* in_sizes, int n_in,
                              void* d_out, int out_size) {
    const float* node_feat = (const float*)d_in[0];
    const float* edge_feat = (const float*)d_in[1];
    const float* edge_dist = (const float*)d_in[2];
    const int* src = (const int*)d_in[3];
    const int* dst = (const int*)d_in[4];

    const float* w_enc1 = (const float*)d_in[5];
    const float* b_enc1 = (const float*)d_in[6];
    const float* w_enc2 = (const float*)d_in[7];
    const float* b_enc2 = (const float*)d_in[8];
    const float* w_enc3 = (const float*)d_in[9];
    const float* b_enc3 = (const float*)d_in[10];

    const float* w_dec1 = (const float*)d_in[11];
    const float* b_dec1 = (const float*)d_in[12];
    const float* w_dec2 = (const float*)d_in[13];
    const float* b_dec2 = (const float*)d_in[14];
    const float* w_dec3 = (const float*)d_in[15];
    const float* b_dec3 = (const float*)d_in[16];

    const float* w_nod1 = (const float*)d_in[17];
    const float* b_nod1 = (const float*)d_in[18];
    const float* w_nod2 = (const float*)d_in[19];
    const float* b_nod2 = (const float*)d_in[20];
    const float* w_nod3 = (const float*)d_in[21];
    const float* b_nod3 = (const float*)d_in[22];

    const float* w_edg1 = (const float*)d_in[23];
    const float* b_edg1 = (const float*)d_in[24];
    const float* w_edg2 = (const float*)d_in[25];
    const float* b_edg2 = (const float*)d_in[26];
    const float* w_edg3 = (const float*)d_in[27];
    const float* b_edg3 = (const float*)d_in[28];

    int N = in_sizes[0] / 3;
    int E = in_sizes[1];

    float *hA, *hB, *wbuf, *hebuf, *aggbuf, *sbuf;
    unsigned* mbuf;
    cudaGetSymbolAddress((void**)&hA, g_hA);
    cudaGetSymbolAddress((void**)&hB, g_hB);
    cudaGetSymbolAddress((void**)&wbuf, g_w);
    cudaGetSymbolAddress((void**)&hebuf, g_he);
    cudaGetSymbolAddress((void**)&aggbuf, g_agg);
    cudaGetSymbolAddress((void**)&sbuf, g_s);
    cudaGetSymbolAddress((void**)&mbuf, g_m);

    int gN128 = (N + 127) / 128;
    int gN8 = (N * 8 + 255) / 256;
    int gE = (E + 255) / 256;
    int gE2 = (E + 255) / 256;  // edge MLP: 128 thr x 2 edges = 256 edges/blk

    // encoder: [N,3] -> hA [N,8]
    k_node_mlp<3, 3, 8><<<gN128, 128>>>(node_feat, nullptr, w_enc1, b_enc1,
                                        w_enc2, b_enc2, w_enc3, b_enc3, hA, N);

    // edge softmax (unnormalized weights in wbuf, sums in sbuf)
    cudaMemsetAsync(mbuf, 0, (size_t)N * 4);
    k_segmax<<<gE, 256>>>(edge_dist, dst, mbuf, E);
    cudaMemsetAsync(sbuf, 0, (size_t)N * 4);
    k_segexp<<<gE, 256>>>(edge_dist, dst, mbuf, wbuf, sbuf, E);

    // h = segsum(w * hA[src], dst) / s -> hB
    cudaMemsetAsync(hB, 0, (size_t)N * 8 * 4);
    k_agg8<<<gE, 256>>>(wbuf, hA, src, dst, hB, E);
    k_scale8<<<gN8, 256>>>(hB, sbuf, N);

    // iteration 1 (h = hB, he = edge_feat)
    cudaMemsetAsync(aggbuf, 0, (size_t)N * 4);
    k_edge_mlp<<<gE2, 128>>>(edge_feat, hB, src, dst, w_edg1, b_edg1, w_edg2,
                             b_edg2, w_edg3, b_edg3, hebuf, aggbuf, E);
    k_node_mlp<9, 1, 8><<<gN128, 128>>>(aggbuf, hB, w_nod1, b_nod1, w_nod2,
                                        b_nod2, w_nod3, b_nod3, hA, N);

    // iteration 2 (h = hA, he = hebuf)
    cudaMemsetAsync(aggbuf, 0, (size_t)N * 4);
    k_edge_mlp<<<gE2, 128>>>(hebuf, hA, src, dst, w_edg1, b_edg1, w_edg2,
                             b_edg2, w_edg3, b_edg3, hebuf, aggbuf, E);
    k_node_mlp<9, 1, 8><<<gN128, 128>>>(aggbuf, hA, w_nod1, b_nod1, w_nod2,
                                        b_nod2, w_nod3, b_nod3, hB, N);

    // final softmax aggregation: hA = segsum(w * hB[src], dst) / s
    cudaMemsetAsync(hA, 0, (size_t)N * 8 * 4);
    k_agg8<<<gE, 256>>>(wbuf, hB, src, dst, hA, E);
    k_scale8<<<gN8, 256>>>(hA, sbuf, N);

    // decoder: hA [N,8] -> out [N,1]
    k_node_mlp<8, 8, 1><<<gN128, 128>>>(hA, nullptr, w_dec1, b_dec1, w_dec2,
                                        b_dec2, w_dec3, b_dec3, (float*)d_out,
                                        N);
}